// round 6
// baseline (speedup 1.0000x reference)
#include <cuda_runtime.h>
#include <math.h>

#define B_DIM 64
#define K_DIM 128
#define H_DIM 64
#define W_DIM 64
#define PLANE (H_DIM * W_DIM)          // 4096 floats
#define N_PLANES (B_DIM * K_DIM)       // 8192
#define N_BOXES 256
#define ALPHA 1.0f
#define BETA 0.5f
#define NPART 32
#define PART_STRIDE 32                 // 128B between accumulator slots
#define MAX_BOXES_PER_PLANE 16

// Zero-initialized device globals; last block resets them each run.
__device__ float g_cls_parts[NPART * PART_STRIDE];
__device__ float g_loc_parts[NPART * PART_STRIDE];
__device__ unsigned int g_done_count;

__device__ __forceinline__ float softplus_f(float x) {
    float ax = fabsf(x);
    return log1pf(expf(-ax)) + fmaxf(x, 0.0f);
}

// One CTA per (b,k) plane. Streams the plane once; computes the plane max
// (cls BCE) AND the loc sums for any boxes referencing this plane, directly
// from register-resident data.
__global__ __launch_bounds__(256) void fused_kernel(
    const float* __restrict__ cams,
    const float* __restrict__ concepts_gt,
    const int* __restrict__ box_b,
    const int* __restrict__ box_c,
    const int* __restrict__ y0v,
    const int* __restrict__ y1v,
    const int* __restrict__ x0v,
    const int* __restrict__ x1v,
    float* __restrict__ out)
{
    int plane = blockIdx.x;
    const float4* p = reinterpret_cast<const float4*>(cams + (size_t)plane * PLANE);

    int t = threadIdx.x;
    int wid = t >> 5, lid = t & 31;

    __shared__ float sm[8];
    __shared__ float si[8], so[8];
    __shared__ int s_cnt;
    __shared__ int s_list[MAX_BOXES_PER_PLANE];

    if (t == 0) s_cnt = 0;

    // ---- load 16 values, keep in registers ----
    float4 v0 = p[0 * 256 + t];
    float4 v1 = p[1 * 256 + t];
    float4 v2 = p[2 * 256 + t];
    float4 v3 = p[3 * 256 + t];

    // ---- box matching: thread t tests box t ----
    if (t < N_BOXES) {
        if (box_b[t] * K_DIM + box_c[t] == plane) {
            int pos = atomicAdd(&s_cnt, 1);
            if (pos < MAX_BOXES_PER_PLANE) s_list[pos] = t;
        }
    }

    // ---- block max ----
    float m = fmaxf(fmaxf(fmaxf(v0.x, v0.y), fmaxf(v0.z, v0.w)),
                    fmaxf(fmaxf(v1.x, v1.y), fmaxf(v1.z, v1.w)));
    m = fmaxf(m, fmaxf(fmaxf(fmaxf(v2.x, v2.y), fmaxf(v2.z, v2.w)),
                       fmaxf(fmaxf(v3.x, v3.y), fmaxf(v3.z, v3.w))));
#pragma unroll
    for (int off = 16; off > 0; off >>= 1)
        m = fmaxf(m, __shfl_xor_sync(0xFFFFFFFFu, m, off));
    if (lid == 0) sm[wid] = m;
    __syncthreads();      // also publishes s_cnt / s_list

    if (t == 0) {
        float bm = sm[0];
#pragma unroll
        for (int w = 1; w < 8; w++) bm = fmaxf(bm, sm[w]);
        float y = concepts_gt[plane];
        float bce = y * softplus_f(-bm) + (1.0f - y) * softplus_f(bm);
        atomicAdd(&g_cls_parts[(plane & (NPART - 1)) * PART_STRIDE], bce);
    }

    // ---- loc path for matched boxes (expected ~1 per 32 blocks) ----
    int nbox = min(s_cnt, MAX_BOXES_PER_PLANE);
    for (int bi = 0; bi < nbox; bi++) {
        int box = s_list[bi];
        int y0 = y0v[box], y1 = y1v[box], x0 = x0v[box], x1 = x1v[box];

        float inside = 0.0f, outside = 0.0f;
        float4 vv[4] = {v0, v1, v2, v3};
#pragma unroll
        for (int i = 0; i < 4; i++) {
            int u = i * 256 + t;        // float4 index within plane
            int row = u >> 4;           // 16 float4 per row
            int col0 = (u & 15) << 2;
            bool rin = (row >= y0) && (row < y1);
            float vals[4] = {vv[i].x, vv[i].y, vv[i].z, vv[i].w};
#pragma unroll
            for (int j = 0; j < 4; j++) {
                int col = col0 + j;
                float e = __expf(-vals[j]);
                float s = __fdividef(1.0f, 1.0f + e);
                bool in = rin && (col >= x0) && (col < x1);
                float d = s - 1.0f;
                if (in) inside += d * d;
                else    outside += s * s;
            }
        }
#pragma unroll
        for (int off = 16; off > 0; off >>= 1) {
            inside  += __shfl_xor_sync(0xFFFFFFFFu, inside, off);
            outside += __shfl_xor_sync(0xFFFFFFFFu, outside, off);
        }
        __syncthreads();                 // protect si/so reuse across boxes
        if (lid == 0) { si[wid] = inside; so[wid] = outside; }
        __syncthreads();
        if (t == 0) {
            float ti = 0.0f, to = 0.0f;
#pragma unroll
            for (int w = 0; w < 8; w++) { ti += si[w]; to += so[w]; }
            float area = (float)((y1 - y0) * (x1 - x0));
            const float eps = 1e-6f;
            float loss = ti / (area + eps) + to / ((float)PLANE - area + eps);
            atomicAdd(&g_loc_parts[(box & (NPART - 1)) * PART_STRIDE], loss);
        }
    }

    // ---- last-block finalize ----
    if (t == 0) {
        __threadfence();
        unsigned int prev = atomicAdd(&g_done_count, 1u);
        if (prev == N_PLANES - 1) {
            float cls = 0.0f, loc = 0.0f;
#pragma unroll
            for (int i = 0; i < NPART; i++) {
                cls += g_cls_parts[i * PART_STRIDE];
                loc += g_loc_parts[i * PART_STRIDE];
                g_cls_parts[i * PART_STRIDE] = 0.0f;
                g_loc_parts[i * PART_STRIDE] = 0.0f;
            }
            out[0] = ALPHA * (cls / (float)N_PLANES) + BETA * (loc / (float)N_BOXES);
            g_done_count = 0u;   // reset for next graph replay
        }
    }
}

extern "C" void kernel_launch(void* const* d_in, const int* in_sizes, int n_in,
                              void* d_out, int out_size) {
    const float* cams        = (const float*)d_in[0];
    const float* concepts_gt = (const float*)d_in[1];
    const int*   box_b       = (const int*)d_in[2];
    const int*   box_c       = (const int*)d_in[3];
    const int*   y0          = (const int*)d_in[4];
    const int*   y1          = (const int*)d_in[5];
    const int*   x0          = (const int*)d_in[6];
    const int*   x1          = (const int*)d_in[7];
    float* out = (float*)d_out;

    fused_kernel<<<N_PLANES, 256>>>(cams, concepts_gt, box_b, box_c,
                                    y0, y1, x0, x1, out);
}

// round 7
// speedup vs baseline: 1.1846x; 1.1846x over previous
#include <cuda_runtime.h>
#include <math.h>

#define B_DIM 64
#define K_DIM 128
#define H_DIM 64
#define W_DIM 64
#define PLANE (H_DIM * W_DIM)          // 4096 floats
#define N_PLANES (B_DIM * K_DIM)       // 8192
#define N_BOXES 256
#define N_BLOCKS (N_PLANES + N_BOXES)  // 8448
#define ALPHA 1.0f
#define BETA 0.5f
#define NPART 32
#define PART_STRIDE 32                 // 128B between accumulator slots

// Zero-initialized device globals; finalizer block resets them each run.
__device__ float g_cls_parts[NPART * PART_STRIDE];
__device__ float g_loc_parts[NPART * PART_STRIDE];
__device__ unsigned int g_done_count;

__device__ __forceinline__ float softplus_f(float x) {
    float ax = fabsf(x);
    return log1pf(expf(-ax)) + fmaxf(x, 0.0f);
}

// Release-scoped fetch-add: orders this block's prior global writes without
// the CCTL.IVALL/L1-flush a full __threadfence() would cost.
__device__ __forceinline__ unsigned int atom_add_release_gpu(unsigned int* addr, unsigned int v) {
    unsigned int old;
    asm volatile("atom.release.gpu.global.add.u32 %0, [%1], %2;"
                 : "=r"(old) : "l"(addr), "r"(v) : "memory");
    return old;
}

__global__ __launch_bounds__(256) void fused_loss_kernel(
    const float* __restrict__ cams,
    const float* __restrict__ concepts_gt,
    const int* __restrict__ box_b,
    const int* __restrict__ box_c,
    const int* __restrict__ y0v,
    const int* __restrict__ y1v,
    const int* __restrict__ x0v,
    const int* __restrict__ x1v,
    float* __restrict__ out)
{
    int t = threadIdx.x;
    int wid = t >> 5, lid = t & 31;
    __shared__ float s0[8], s1[8];

    if (blockIdx.x < N_BOXES) {
        // ---------------- loc path: one block per box ----------------
        int box = blockIdx.x;
        int b = box_b[box];
        int c = box_c[box];
        int y0 = y0v[box], y1 = y1v[box], x0 = x0v[box], x1 = x1v[box];

        const float4* p = reinterpret_cast<const float4*>(
            cams + ((size_t)b * K_DIM + c) * PLANE);

        float inside = 0.0f, outside = 0.0f;
#pragma unroll
        for (int i = 0; i < 4; i++) {
            int u = i * 256 + t;        // float4 index within plane [0,1024)
            float4 v = p[u];
            int row = u >> 4;           // 16 float4 per row (W=64)
            int col0 = (u & 15) << 2;
            float vals[4] = {v.x, v.y, v.z, v.w};
            bool rin = (row >= y0) && (row < y1);
#pragma unroll
            for (int j = 0; j < 4; j++) {
                int col = col0 + j;
                float e = __expf(-vals[j]);
                float s = __fdividef(1.0f, 1.0f + e);
                bool in = rin && (col >= x0) && (col < x1);
                float d = s - 1.0f;
                if (in) inside += d * d;
                else    outside += s * s;
            }
        }
#pragma unroll
        for (int off = 16; off > 0; off >>= 1) {
            inside  += __shfl_xor_sync(0xFFFFFFFFu, inside, off);
            outside += __shfl_xor_sync(0xFFFFFFFFu, outside, off);
        }
        if (lid == 0) { s0[wid] = inside; s1[wid] = outside; }
        __syncthreads();
        if (t == 0) {
            float ti = 0.0f, to = 0.0f;
#pragma unroll
            for (int w = 0; w < 8; w++) { ti += s0[w]; to += s1[w]; }
            float area = (float)((y1 - y0) * (x1 - x0));
            const float eps = 1e-6f;
            float loss = ti / (area + eps) + to / ((float)PLANE - area + eps);
            atomicAdd(&g_loc_parts[(box & (NPART - 1)) * PART_STRIDE], loss);
        }
    } else {
        // ---------------- cls path: one block per (b,k) plane ----------------
        int plane = blockIdx.x - N_BOXES;
        const float4* p = reinterpret_cast<const float4*>(cams + (size_t)plane * PLANE);

        float m = -INFINITY;
#pragma unroll
        for (int i = 0; i < 4; i++) {
            float4 v = p[i * 256 + t];
            m = fmaxf(m, fmaxf(fmaxf(v.x, v.y), fmaxf(v.z, v.w)));
        }
#pragma unroll
        for (int off = 16; off > 0; off >>= 1)
            m = fmaxf(m, __shfl_xor_sync(0xFFFFFFFFu, m, off));
        if (lid == 0) s0[wid] = m;
        __syncthreads();
        if (t == 0) {
            float bm = s0[0];
#pragma unroll
            for (int w = 1; w < 8; w++) bm = fmaxf(bm, s0[w]);
            float y = concepts_gt[plane];
            float bce = y * softplus_f(-bm) + (1.0f - y) * softplus_f(bm);
            atomicAdd(&g_cls_parts[(plane & (NPART - 1)) * PART_STRIDE], bce);
        }
    }

    // ---------------- completion + last-block finalize ----------------
    // Release-RED orders this block's part-atomicAdd before the counter bump;
    // no per-block L1 flush.
    if (t == 0) {
        unsigned int prev = atom_add_release_gpu(&g_done_count, 1u);
        if (prev == N_BLOCKS - 1) {
            // One acquire fence in ONE block total.
            asm volatile("fence.acq_rel.gpu;" ::: "memory");
            float cls = 0.0f, loc = 0.0f;
#pragma unroll
            for (int i = 0; i < NPART; i++) {
                cls += g_cls_parts[i * PART_STRIDE];
                loc += g_loc_parts[i * PART_STRIDE];
                g_cls_parts[i * PART_STRIDE] = 0.0f;
                g_loc_parts[i * PART_STRIDE] = 0.0f;
            }
            out[0] = ALPHA * (cls / (float)N_PLANES) + BETA * (loc / (float)N_BOXES);
            g_done_count = 0u;   // reset for next graph replay
        }
    }
}

extern "C" void kernel_launch(void* const* d_in, const int* in_sizes, int n_in,
                              void* d_out, int out_size) {
    const float* cams        = (const float*)d_in[0];
    const float* concepts_gt = (const float*)d_in[1];
    const int*   box_b       = (const int*)d_in[2];
    const int*   box_c       = (const int*)d_in[3];
    const int*   y0          = (const int*)d_in[4];
    const int*   y1          = (const int*)d_in[5];
    const int*   x0          = (const int*)d_in[6];
    const int*   x1          = (const int*)d_in[7];
    float* out = (float*)d_out;

    fused_loss_kernel<<<N_BLOCKS, 256>>>(cams, concepts_gt, box_b, box_c,
                                         y0, y1, x0, x1, out);
}

// round 8
// speedup vs baseline: 1.2793x; 1.0800x over previous
#include <cuda_runtime.h>
#include <math.h>

#define B_DIM 64
#define K_DIM 128
#define H_DIM 64
#define W_DIM 64
#define PLANE (H_DIM * W_DIM)          // 4096 floats
#define N_PLANES (B_DIM * K_DIM)       // 8192
#define N_BOXES 256
#define N_TASKS (N_PLANES + N_BOXES)   // 8448
#define GRID 1056                       // one wave: ~7.1 CTAs/SM
#define ITERS (N_TASKS / GRID)          // 8 tasks per CTA, exact
#define ALPHA 1.0f
#define BETA 0.5f
#define NPART 32
#define PART_STRIDE 32                 // 128B between accumulator slots

// Zero-initialized device globals; finalizer CTA resets them each run.
__device__ float g_cls_parts[NPART * PART_STRIDE];
__device__ float g_loc_parts[NPART * PART_STRIDE];
__device__ unsigned int g_done_count;

__device__ __forceinline__ float softplus_f(float x) {
    float ax = fabsf(x);
    return log1pf(expf(-ax)) + fmaxf(x, 0.0f);
}

// Release-scoped fetch-add: orders this CTA's prior global atomics without a
// full __threadfence() (no CCTL.IVALL L1 flush).
__device__ __forceinline__ unsigned int atom_add_release_gpu(unsigned int* addr, unsigned int v) {
    unsigned int old;
    asm volatile("atom.release.gpu.global.add.u32 %0, [%1], %2;"
                 : "=r"(old) : "l"(addr), "r"(v) : "memory");
    return old;
}

__global__ __launch_bounds__(256) void fused_loss_kernel(
    const float* __restrict__ cams,
    const float* __restrict__ concepts_gt,
    const int* __restrict__ box_b,
    const int* __restrict__ box_c,
    const int* __restrict__ y0v,
    const int* __restrict__ y1v,
    const int* __restrict__ x0v,
    const int* __restrict__ x1v,
    float* __restrict__ out)
{
    int t = threadIdx.x;
    int wid = t >> 5, lid = t & 31;
    __shared__ float s0[8], s1[8];

    float cls_local = 0.0f;   // meaningful in t==0 only
    float loc_local = 0.0f;

#pragma unroll
    for (int it = 0; it < ITERS; it++) {
        int task = blockIdx.x + it * GRID;

        if (task < N_BOXES) {
            // -------- loc task: this CTA handles one box --------
            int box = task;
            int b = box_b[box];
            int c = box_c[box];
            int y0 = y0v[box], y1 = y1v[box], x0 = x0v[box], x1 = x1v[box];

            const float4* p = reinterpret_cast<const float4*>(
                cams + ((size_t)b * K_DIM + c) * PLANE);

            float inside = 0.0f, outside = 0.0f;
#pragma unroll
            for (int i = 0; i < 4; i++) {
                int u = i * 256 + t;        // float4 index within plane
                float4 v = p[u];
                int row = u >> 4;           // 16 float4 per row (W=64)
                int col0 = (u & 15) << 2;
                float vals[4] = {v.x, v.y, v.z, v.w};
                bool rin = (row >= y0) && (row < y1);
#pragma unroll
                for (int j = 0; j < 4; j++) {
                    int col = col0 + j;
                    float e = __expf(-vals[j]);
                    float s = __fdividef(1.0f, 1.0f + e);
                    bool in = rin && (col >= x0) && (col < x1);
                    float d = s - 1.0f;
                    if (in) inside += d * d;
                    else    outside += s * s;
                }
            }
#pragma unroll
            for (int off = 16; off > 0; off >>= 1) {
                inside  += __shfl_xor_sync(0xFFFFFFFFu, inside, off);
                outside += __shfl_xor_sync(0xFFFFFFFFu, outside, off);
            }
            if (lid == 0) { s0[wid] = inside; s1[wid] = outside; }
            __syncthreads();
            if (t == 0) {
                float ti = 0.0f, to = 0.0f;
#pragma unroll
                for (int w = 0; w < 8; w++) { ti += s0[w]; to += s1[w]; }
                float area = (float)((y1 - y0) * (x1 - x0));
                const float eps = 1e-6f;
                loc_local += ti / (area + eps) + to / ((float)PLANE - area + eps);
            }
            __syncthreads();            // s0/s1 reuse guard
        } else {
            // -------- cls task: one (b,k) plane max + BCE --------
            int plane = task - N_BOXES;
            const float4* p = reinterpret_cast<const float4*>(cams + (size_t)plane * PLANE);

            float m = -INFINITY;
#pragma unroll
            for (int i = 0; i < 4; i++) {
                float4 v = p[i * 256 + t];
                m = fmaxf(m, fmaxf(fmaxf(v.x, v.y), fmaxf(v.z, v.w)));
            }
#pragma unroll
            for (int off = 16; off > 0; off >>= 1)
                m = fmaxf(m, __shfl_xor_sync(0xFFFFFFFFu, m, off));
            if (lid == 0) s0[wid] = m;
            __syncthreads();
            if (t == 0) {
                float bm = s0[0];
#pragma unroll
                for (int w = 1; w < 8; w++) bm = fmaxf(bm, s0[w]);
                float y = concepts_gt[plane];
                cls_local += y * softplus_f(-bm) + (1.0f - y) * softplus_f(bm);
            }
            __syncthreads();            // s0 reuse guard
        }
    }

    // -------- one epilogue per CTA --------
    if (t == 0) {
        int slot = (blockIdx.x & (NPART - 1)) * PART_STRIDE;
        atomicAdd(&g_cls_parts[slot], cls_local);
        atomicAdd(&g_loc_parts[slot], loc_local);

        unsigned int prev = atom_add_release_gpu(&g_done_count, 1u);
        if (prev == GRID - 1) {
            asm volatile("fence.acq_rel.gpu;" ::: "memory");
            float cls = 0.0f, loc = 0.0f;
#pragma unroll
            for (int i = 0; i < NPART; i++) {
                cls += g_cls_parts[i * PART_STRIDE];
                loc += g_loc_parts[i * PART_STRIDE];
                g_cls_parts[i * PART_STRIDE] = 0.0f;
                g_loc_parts[i * PART_STRIDE] = 0.0f;
            }
            out[0] = ALPHA * (cls / (float)N_PLANES) + BETA * (loc / (float)N_BOXES);
            g_done_count = 0u;   // reset for next graph replay
        }
    }
}

extern "C" void kernel_launch(void* const* d_in, const int* in_sizes, int n_in,
                              void* d_out, int out_size) {
    const float* cams        = (const float*)d_in[0];
    const float* concepts_gt = (const float*)d_in[1];
    const int*   box_b       = (const int*)d_in[2];
    const int*   box_c       = (const int*)d_in[3];
    const int*   y0          = (const int*)d_in[4];
    const int*   y1          = (const int*)d_in[5];
    const int*   x0          = (const int*)d_in[6];
    const int*   x1          = (const int*)d_in[7];
    float* out = (float*)d_out;

    fused_loss_kernel<<<GRID, 256>>>(cams, concepts_gt, box_b, box_c,
                                     y0, y1, x0, x1, out);
}